// round 3
// baseline (speedup 1.0000x reference)
#include <cuda_runtime.h>
#include <cstdint>

// GCNAggregator: out[b,t,o] = relu( mean_s(features[sample[b,t,s], :]) @ W )
// features: [100000, 128] f32   (12,800,000 elems)
// sample:   [8, 4096, 25] int   (819,200 elems; harness narrows int64->int32)
// W:        [128, 128] f32      (16,384 elems)
// out:      [32768, 128] f32

#define ROWS_PER_BLOCK 16
#define THREADS 256
#define D 128
#define S_SAMPLES 25
#define N_NODES 100000

__global__ __launch_bounds__(THREADS)
void gcn_agg_kernel(const float* __restrict__ features,
                    const int* __restrict__ sample,
                    const float* __restrict__ W,
                    float* __restrict__ out)
{
    extern __shared__ float smem[];
    float* sW    = smem;                 // [128*128] = 64 KB
    float* sMean = smem + D * D;         // [ROWS_PER_BLOCK * 128] = 8 KB

    const int tid  = threadIdx.x;
    const int warp = tid >> 5;
    const int lane = tid & 31;
    const int row0 = blockIdx.x * ROWS_PER_BLOCK;

    // ---- Stage W into shared (vectorized, coalesced) ----
    #pragma unroll
    for (int i = tid * 4; i < D * D; i += THREADS * 4) {
        *reinterpret_cast<float4*>(&sW[i]) =
            *reinterpret_cast<const float4*>(&W[i]);
    }

    // ---- Phase A: gather + mean. Each warp handles 2 rows. ----
    // Lane owns a float4 slice of the 128-dim feature vector.
    for (int rr = warp; rr < ROWS_PER_BLOCK; rr += (THREADS / 32)) {
        const int row = row0 + rr;
        const int* idxp = sample + (long long)row * S_SAMPLES;

        float4 acc = make_float4(0.f, 0.f, 0.f, 0.f);
        #pragma unroll
        for (int s = 0; s < S_SAMPLES; s++) {
            // same address across lanes -> single broadcast request
            int node = __ldg(&idxp[s]);
            // defensive clamp: converts any dtype-misread into finite error
            node = min(max(node, 0), N_NODES - 1);
            const float4 v = *reinterpret_cast<const float4*>(
                &features[(long long)node * D + lane * 4]);
            acc.x += v.x; acc.y += v.y; acc.z += v.z; acc.w += v.w;
        }
        const float inv = 1.0f / (float)S_SAMPLES;
        acc.x *= inv; acc.y *= inv; acc.z *= inv; acc.w *= inv;
        *reinterpret_cast<float4*>(&sMean[rr * D + lane * 4]) = acc;
    }
    __syncthreads();

    // ---- Phase B: [16,128] @ [128,128] + relu ----
    // Thread computes 8 rows x 1 output column.
    const int o     = tid & (D - 1);     // coalesced W reads + out writes
    const int rbase = (tid >> 7) * 8;    // rows [0..7] or [8..15]

    float acc[8];
    #pragma unroll
    for (int j = 0; j < 8; j++) acc[j] = 0.f;

    #pragma unroll 4
    for (int d = 0; d < D; d++) {
        const float w = sW[d * D + o];          // conflict-free across warp
        #pragma unroll
        for (int j = 0; j < 8; j++) {
            // broadcast read within warp (all lanes same address)
            acc[j] = fmaf(sMean[(rbase + j) * D + d], w, acc[j]);
        }
    }

    #pragma unroll
    for (int j = 0; j < 8; j++) {
        const long long r = (long long)(row0 + rbase + j);
        out[r * D + o] = fmaxf(acc[j], 0.0f);
    }
}

extern "C" void kernel_launch(void* const* d_in, const int* in_sizes, int n_in,
                              void* d_out, int out_size)
{
    // Identify inputs by element count — robust to d_in ordering.
    // features: 12,800,000 (largest), sample: 819,200, weights: 16,384 (smallest).
    int imax = 0, imin = 0;
    for (int i = 1; i < 3 && i < n_in; i++) {
        if (in_sizes[i] > in_sizes[imax]) imax = i;
        if (in_sizes[i] < in_sizes[imin]) imin = i;
    }
    const int imid = 3 - imax - imin;  // indices {0,1,2}

    const float* features = (const float*)d_in[imax];
    const float* W        = (const float*)d_in[imin];
    const int*   sample   = (const int*)d_in[imid];   // int32 per harness contract
    const int sample_elems = in_sizes[imid];

    float* out = (float*)d_out;

    const int n_rows = sample_elems / S_SAMPLES;     // 32768
    const int grid   = n_rows / ROWS_PER_BLOCK;      // 2048

    const int smem_bytes = (D * D + ROWS_PER_BLOCK * D) * sizeof(float); // 73728

    cudaFuncSetAttribute(gcn_agg_kernel,
                         cudaFuncAttributeMaxDynamicSharedMemorySize,
                         smem_bytes);

    gcn_agg_kernel<<<grid, THREADS, smem_bytes>>>(features, sample, W, out);
}

// round 4
// speedup vs baseline: 1.4946x; 1.4946x over previous
#include <cuda_runtime.h>
#include <cstdint>

// GCNAggregator: out[b,t,o] = relu( mean_s(features[sample[b,t,s], :]) @ W )
// features: [100000, 128] f32   (12,800,000 elems)
// sample:   [8, 4096, 25] int32 (819,200 elems)
// W:        [128, 128] f32      (16,384 elems)
// out:      [32768, 128] f32

#define ROWS_PER_BLOCK 64
#define THREADS 512
#define D 128
#define S_SAMPLES 25
#define N_NODES 100000
#define SM_STRIDE 132   // padded sMean row stride (floats); %4==0 for float4 STS

__global__ __launch_bounds__(THREADS, 2)
void gcn_agg_kernel(const float* __restrict__ features,
                    const int* __restrict__ sample,
                    const float* __restrict__ W,
                    float* __restrict__ out)
{
    extern __shared__ float smem[];
    float* sW    = smem;                          // 128*128 floats = 64 KB
    float* sMean = smem + D * D;                  // 64*132 floats  = 33.8 KB

    const int tid  = threadIdx.x;
    const int warp = tid >> 5;        // 0..15
    const int lane = tid & 31;
    const int row0 = blockIdx.x * ROWS_PER_BLOCK;

    // ---- Stage W into shared (vectorized, coalesced) ----
    #pragma unroll
    for (int i = tid * 4; i < D * D; i += THREADS * 4) {
        *reinterpret_cast<float4*>(&sW[i]) =
            *reinterpret_cast<const float4*>(&W[i]);
    }

    // ---- Phase A: gather + mean. 16 warps, 64 rows -> 4 rows/warp. ----
    // Lane owns a float4 slice of the 128-dim feature vector.
    #pragma unroll
    for (int rr = warp; rr < ROWS_PER_BLOCK; rr += (THREADS / 32)) {
        const int row = row0 + rr;
        const int* idxp = sample + (long long)row * S_SAMPLES;

        float4 acc = make_float4(0.f, 0.f, 0.f, 0.f);
        #pragma unroll
        for (int s = 0; s < S_SAMPLES; s++) {
            int node = __ldg(&idxp[s]);                    // broadcast
            node = min(max(node, 0), N_NODES - 1);         // defensive clamp
            const float4 v = *reinterpret_cast<const float4*>(
                &features[(long long)node * D + lane * 4]);
            acc.x += v.x; acc.y += v.y; acc.z += v.z; acc.w += v.w;
        }
        const float inv = 1.0f / (float)S_SAMPLES;
        acc.x *= inv; acc.y *= inv; acc.z *= inv; acc.w *= inv;
        *reinterpret_cast<float4*>(&sMean[rr * SM_STRIDE + lane * 4]) = acc;
    }
    __syncthreads();

    // ---- Phase B: [64,128] @ [128,128] + relu, packed f32x2 FMA ----
    // Warp w owns rows [w*4, w*4+4) x all 128 cols.
    // Thread: 4 rows x 4 cols (cols = lane*4 .. +3, contiguous float4).
    // Per d: 1 LDS.128 (sW, conflict-free) + 4 broadcast scalar LDS (sMean).
    const int r0 = warp * 4;
    const int c0 = lane * 4;

    unsigned long long acc[4][2];
    #pragma unroll
    for (int j = 0; j < 4; j++) { acc[j][0] = 0ull; acc[j][1] = 0ull; }

    #pragma unroll 4
    for (int d = 0; d < D; d++) {
        // b: two packed f32 pairs from one LDS.128
        const longlong2 bl = *reinterpret_cast<const longlong2*>(
            &sW[d * D + c0]);
        const unsigned long long b01 = (unsigned long long)bl.x;
        const unsigned long long b23 = (unsigned long long)bl.y;

        #pragma unroll
        for (int j = 0; j < 4; j++) {
            const float a = sMean[(r0 + j) * SM_STRIDE + d];   // broadcast
            unsigned long long a2;
            asm("mov.b64 %0, {%1, %1};" : "=l"(a2) : "f"(a));  // splat
            asm("fma.rn.f32x2 %0, %1, %2, %0;"
                : "+l"(acc[j][0]) : "l"(a2), "l"(b01));
            asm("fma.rn.f32x2 %0, %1, %2, %0;"
                : "+l"(acc[j][1]) : "l"(a2), "l"(b23));
        }
    }

    // ---- Epilogue: unpack, relu, coalesced float4 stores ----
    #pragma unroll
    for (int j = 0; j < 4; j++) {
        float4 o4;
        asm("mov.b64 {%0, %1}, %2;" : "=f"(o4.x), "=f"(o4.y) : "l"(acc[j][0]));
        asm("mov.b64 {%0, %1}, %2;" : "=f"(o4.z), "=f"(o4.w) : "l"(acc[j][1]));
        o4.x = fmaxf(o4.x, 0.f); o4.y = fmaxf(o4.y, 0.f);
        o4.z = fmaxf(o4.z, 0.f); o4.w = fmaxf(o4.w, 0.f);
        const long long r = (long long)(row0 + r0 + j);
        *reinterpret_cast<float4*>(&out[r * D + c0]) = o4;
    }
}

extern "C" void kernel_launch(void* const* d_in, const int* in_sizes, int n_in,
                              void* d_out, int out_size)
{
    // Identify inputs by element count — robust to d_in ordering.
    int imax = 0, imin = 0;
    for (int i = 1; i < 3 && i < n_in; i++) {
        if (in_sizes[i] > in_sizes[imax]) imax = i;
        if (in_sizes[i] < in_sizes[imin]) imin = i;
    }
    const int imid = 3 - imax - imin;

    const float* features = (const float*)d_in[imax];
    const float* W        = (const float*)d_in[imin];
    const int*   sample   = (const int*)d_in[imid];
    const int sample_elems = in_sizes[imid];

    float* out = (float*)d_out;

    const int n_rows = sample_elems / S_SAMPLES;        // 32768
    const int grid   = n_rows / ROWS_PER_BLOCK;         // 512

    const int smem_bytes =
        (D * D + ROWS_PER_BLOCK * SM_STRIDE) * sizeof(float);  // 99,328 B

    cudaFuncSetAttribute(gcn_agg_kernel,
                         cudaFuncAttributeMaxDynamicSharedMemorySize,
                         smem_bytes);

    gcn_agg_kernel<<<grid, THREADS, smem_bytes>>>(features, sample, W, out);
}

// round 5
// speedup vs baseline: 1.5606x; 1.0441x over previous
#include <cuda_runtime.h>
#include <cstdint>

// GCNAggregator: out[b,t,o] = relu( mean_s(features[sample[b,t,s], :]) @ W )
// features: [100000, 128] f32   sample: [32768, 25] int32
// W: [128, 128] f32             out: [32768, 128] f32

#define ROWS_PER_BLOCK 32
#define THREADS 256
#define D 128
#define S_SAMPLES 25
#define N_NODES 100000
#define SM_STRIDE 132   // padded sMean row stride (floats), %4==0

typedef unsigned long long u64;

__global__ __launch_bounds__(THREADS, 2)
void gcn_agg_kernel(const float* __restrict__ features,
                    const int* __restrict__ sample,
                    const float* __restrict__ W,
                    float* __restrict__ out)
{
    extern __shared__ float smem[];
    float* sW    = smem;                          // 128*128 = 64 KB
    float* sMean = smem + D * D;                  // 32*132*4 = 16.5 KB

    const int tid  = threadIdx.x;
    const int warp = tid >> 5;        // 0..7
    const int lane = tid & 31;
    const int row0 = blockIdx.x * ROWS_PER_BLOCK;

    // ---- Stage W into shared (vectorized, coalesced) ----
    #pragma unroll
    for (int i = tid * 4; i < D * D; i += THREADS * 4) {
        *reinterpret_cast<float4*>(&sW[i]) =
            *reinterpret_cast<const float4*>(&W[i]);
    }

    // ---- Phase A: gather + mean. 8 warps x 4 rows each. ----
    #pragma unroll
    for (int rr = warp; rr < ROWS_PER_BLOCK; rr += (THREADS / 32)) {
        const int row = row0 + rr;
        const int* idxp = sample + (long long)row * S_SAMPLES;

        float4 acc = make_float4(0.f, 0.f, 0.f, 0.f);
        #pragma unroll
        for (int s = 0; s < S_SAMPLES; s++) {
            int node = __ldg(&idxp[s]);                    // broadcast
            node = min(max(node, 0), N_NODES - 1);         // defensive clamp
            const float4 v = *reinterpret_cast<const float4*>(
                &features[(long long)node * D + lane * 4]);
            acc.x += v.x; acc.y += v.y; acc.z += v.z; acc.w += v.w;
        }
        const float inv = 1.0f / (float)S_SAMPLES;
        acc.x *= inv; acc.y *= inv; acc.z *= inv; acc.w *= inv;
        *reinterpret_cast<float4*>(&sMean[rr * SM_STRIDE + lane * 4]) = acc;
    }
    __syncthreads();

    // ---- Phase B: [32,128] @ [128,128] + relu ----
    // Warp grid: 4 row-groups (8 rows) x 2 col-groups (64 cols).
    // Thread: 8 rows x 2 cols (f32x2-packed along cols).
    // Per 4 d-steps per warp: 8 broadcast LDS.128 (a) + 4 LDS.64 (b)
    //   = ~16 wavefronts for 32 f32x2 FMAs (0.5 wf/FMA).
    const int rg = warp >> 1;            // 0..3
    const int cg = warp & 1;             // 0..1
    const int r0 = rg * 8;
    const int c  = cg * 64 + lane * 2;   // even -> 8B aligned

    u64 acc[8];
    #pragma unroll
    for (int j = 0; j < 8; j++) acc[j] = 0ull;

    #pragma unroll 2
    for (int d0 = 0; d0 < D; d0 += 4) {
        // a: 4 d-values per row, uniform address across warp (broadcast)
        float4 a4[8];
        #pragma unroll
        for (int j = 0; j < 8; j++)
            a4[j] = *reinterpret_cast<const float4*>(
                &sMean[(r0 + j) * SM_STRIDE + d0]);

        #pragma unroll
        for (int dd = 0; dd < 4; dd++) {
            // b: packed pair of cols, conflict-free LDS.64
            const u64 b2 = *reinterpret_cast<const u64*>(
                &sW[(d0 + dd) * D + c]);

            #pragma unroll
            for (int j = 0; j < 8; j++) {
                const float a = (&a4[j].x)[dd];
                u64 a2;
                asm("mov.b64 %0, {%1, %1};" : "=l"(a2) : "f"(a));  // splat
                asm("fma.rn.f32x2 %0, %1, %2, %0;"
                    : "+l"(acc[j]) : "l"(a2), "l"(b2));
            }
        }
    }

    // ---- Epilogue: unpack, relu, coalesced float2 stores ----
    #pragma unroll
    for (int j = 0; j < 8; j++) {
        float2 o2;
        asm("mov.b64 {%0, %1}, %2;" : "=f"(o2.x), "=f"(o2.y) : "l"(acc[j]));
        o2.x = fmaxf(o2.x, 0.f);
        o2.y = fmaxf(o2.y, 0.f);
        const long long r = (long long)(row0 + r0 + j);
        *reinterpret_cast<float2*>(&out[r * D + c]) = o2;
    }
}

extern "C" void kernel_launch(void* const* d_in, const int* in_sizes, int n_in,
                              void* d_out, int out_size)
{
    // Identify inputs by element count — robust to d_in ordering.
    int imax = 0, imin = 0;
    for (int i = 1; i < 3 && i < n_in; i++) {
        if (in_sizes[i] > in_sizes[imax]) imax = i;
        if (in_sizes[i] < in_sizes[imin]) imin = i;
    }
    const int imid = 3 - imax - imin;

    const float* features = (const float*)d_in[imax];
    const float* W        = (const float*)d_in[imin];
    const int*   sample   = (const int*)d_in[imid];
    const int sample_elems = in_sizes[imid];

    float* out = (float*)d_out;

    const int n_rows = sample_elems / S_SAMPLES;        // 32768
    const int grid   = n_rows / ROWS_PER_BLOCK;         // 1024

    const int smem_bytes =
        (D * D + ROWS_PER_BLOCK * SM_STRIDE) * sizeof(float);  // 82,432 B

    cudaFuncSetAttribute(gcn_agg_kernel,
                         cudaFuncAttributeMaxDynamicSharedMemorySize,
                         smem_bytes);

    gcn_agg_kernel<<<grid, THREADS, smem_bytes>>>(features, sample, W, out);
}

// round 8
// speedup vs baseline: 1.6875x; 1.0813x over previous
#include <cuda_runtime.h>
#include <cuda_bf16.h>
#include <mma.h>
#include <cstdint>

using namespace nvcuda;

// GCNAggregator fused: gather+mean -> bf16-split WMMA GEMM -> relu
// out[row][o] = relu( sum_k mean[row][k] * W[k][o] )
// 3-term split: Ahi*Bhi + Ahi*Blo + Alo*Bhi  (rel err ~1e-5)

#define THREADS 256
#define ROWS 64
#define D_DIM 128
#define S_SAMPLES 25
#define N_NODES 100000
#define LDS_A 136          // smem stride in bf16 elems (row = 272B -> conflict-free ldmatrix)

#define SA_ELEMS (ROWS * LDS_A)      // 8704 bf16
#define SW_ELEMS (D_DIM * LDS_A)     // 17408 bf16

__global__ __launch_bounds__(THREADS, 2)
void gcn_agg_kernel(const float* __restrict__ features,
                    const int* __restrict__ sample,
                    const float* __restrict__ W,
                    float* __restrict__ out)
{
    extern __shared__ __nv_bfloat16 smem[];
    __nv_bfloat16* sAhi = smem;                         // [64][136]
    __nv_bfloat16* sAlo = sAhi + SA_ELEMS;
    __nv_bfloat16* sWhi = sAlo + SA_ELEMS;              // [128][136]
    __nv_bfloat16* sWlo = sWhi + SW_ELEMS;

    const int tid  = threadIdx.x;
    const int wid  = tid >> 5;       // 0..7
    const int lane = tid & 31;
    const int row0 = blockIdx.x * ROWS;

    // ---- Stage W -> bf16 hi/lo smem tiles (coalesced float4 loads) ----
    #pragma unroll
    for (int i = 0; i < 16; i++) {
        const int idx = tid + i * THREADS;        // 0..4095 float4
        const int k   = idx >> 5;                 // 0..127
        const int n0  = (idx & 31) * 4;
        const float4 v = *reinterpret_cast<const float4*>(&W[k * D_DIM + n0]);

        __nv_bfloat16 hx = __float2bfloat16(v.x), hy = __float2bfloat16(v.y);
        __nv_bfloat16 hz = __float2bfloat16(v.z), hw = __float2bfloat16(v.w);
        __nv_bfloat162 hi0 = __nv_bfloat162(hx, hy), hi1 = __nv_bfloat162(hz, hw);
        __nv_bfloat162 lo0 = __nv_bfloat162(
            __float2bfloat16(v.x - __bfloat162float(hx)),
            __float2bfloat16(v.y - __bfloat162float(hy)));
        __nv_bfloat162 lo1 = __nv_bfloat162(
            __float2bfloat16(v.z - __bfloat162float(hz)),
            __float2bfloat16(v.w - __bfloat162float(hw)));

        *reinterpret_cast<__nv_bfloat162*>(&sWhi[k * LDS_A + n0])     = hi0;
        *reinterpret_cast<__nv_bfloat162*>(&sWhi[k * LDS_A + n0 + 2]) = hi1;
        *reinterpret_cast<__nv_bfloat162*>(&sWlo[k * LDS_A + n0])     = lo0;
        *reinterpret_cast<__nv_bfloat162*>(&sWlo[k * LDS_A + n0 + 2]) = lo1;
    }

    // ---- Phase A: gather + mean -> bf16 hi/lo A tiles. 8 warps x 8 rows. ----
    const int k0 = lane * 4;
    #pragma unroll
    for (int rr = wid; rr < ROWS; rr += 8) {
        const int* idxp = sample + (long long)(row0 + rr) * S_SAMPLES;
        float4 acc = make_float4(0.f, 0.f, 0.f, 0.f);
        #pragma unroll
        for (int s = 0; s < S_SAMPLES; s++) {
            int node = __ldg(&idxp[s]);                  // broadcast
            node = min(max(node, 0), N_NODES - 1);       // defensive clamp
            const float4 v = *reinterpret_cast<const float4*>(
                &features[(long long)node * D_DIM + k0]);
            acc.x += v.x; acc.y += v.y; acc.z += v.z; acc.w += v.w;
        }
        const float inv = 1.0f / (float)S_SAMPLES;
        acc.x *= inv; acc.y *= inv; acc.z *= inv; acc.w *= inv;

        __nv_bfloat16 hx = __float2bfloat16(acc.x), hy = __float2bfloat16(acc.y);
        __nv_bfloat16 hz = __float2bfloat16(acc.z), hw = __float2bfloat16(acc.w);
        *reinterpret_cast<__nv_bfloat162*>(&sAhi[rr * LDS_A + k0]) =
            __nv_bfloat162(hx, hy);
        *reinterpret_cast<__nv_bfloat162*>(&sAhi[rr * LDS_A + k0 + 2]) =
            __nv_bfloat162(hz, hw);
        *reinterpret_cast<__nv_bfloat162*>(&sAlo[rr * LDS_A + k0]) =
            __nv_bfloat162(__float2bfloat16(acc.x - __bfloat162float(hx)),
                           __float2bfloat16(acc.y - __bfloat162float(hy)));
        *reinterpret_cast<__nv_bfloat162*>(&sAlo[rr * LDS_A + k0 + 2]) =
            __nv_bfloat162(__float2bfloat16(acc.z - __bfloat162float(hz)),
                           __float2bfloat16(acc.w - __bfloat162float(hw)));
    }
    __syncthreads();

    // ---- Phase B: WMMA GEMM [64,128] x [128,128], 3-term bf16 split ----
    // Warp grid 2x4: warp covers 32 rows x 32 cols (2x2 tiles of 16x16).
    const int wr = (wid >> 2) * 32;   // 0 or 32
    const int wc = (wid & 3) * 32;    // 0,32,64,96

    wmma::fragment<wmma::accumulator, 16, 16, 16, float> acc[2][2];
    #pragma unroll
    for (int i = 0; i < 2; i++)
        #pragma unroll
        for (int j = 0; j < 2; j++)
            wmma::fill_fragment(acc[i][j], 0.0f);

    #pragma unroll
    for (int ks = 0; ks < D_DIM / 16; ks++) {
        wmma::fragment<wmma::matrix_a, 16, 16, 16, __nv_bfloat16,
                       wmma::row_major> aHi[2], aLo[2];
        wmma::fragment<wmma::matrix_b, 16, 16, 16, __nv_bfloat16,
                       wmma::row_major> bHi[2], bLo[2];

        #pragma unroll
        for (int i = 0; i < 2; i++) {
            const __nv_bfloat16* pa = &sAhi[(wr + i * 16) * LDS_A + ks * 16];
            wmma::load_matrix_sync(aHi[i], pa, LDS_A);
            wmma::load_matrix_sync(aLo[i], pa + SA_ELEMS, LDS_A);   // sAlo (FIXED)
        }
        #pragma unroll
        for (int j = 0; j < 2; j++) {
            const __nv_bfloat16* pb = &sWhi[(ks * 16) * LDS_A + wc + j * 16];
            wmma::load_matrix_sync(bHi[j], pb, LDS_A);
            wmma::load_matrix_sync(bLo[j], pb + SW_ELEMS, LDS_A);   // sWlo
        }

        #pragma unroll
        for (int i = 0; i < 2; i++)
            #pragma unroll
            for (int j = 0; j < 2; j++) {
                wmma::mma_sync(acc[i][j], aHi[i], bHi[j], acc[i][j]);
                wmma::mma_sync(acc[i][j], aHi[i], bLo[j], acc[i][j]);
                wmma::mma_sync(acc[i][j], aLo[i], bHi[j], acc[i][j]);
            }
    }

    // ---- Epilogue: relu + direct gmem store ----
    #pragma unroll
    for (int i = 0; i < 2; i++)
        #pragma unroll
        for (int j = 0; j < 2; j++) {
            #pragma unroll
            for (int t = 0; t < acc[i][j].num_elements; t++)
                acc[i][j].x[t] = fmaxf(acc[i][j].x[t], 0.0f);
            wmma::store_matrix_sync(
                &out[(long long)(row0 + wr + i * 16) * D_DIM + wc + j * 16],
                acc[i][j], D_DIM, wmma::mem_row_major);
        }
}

extern "C" void kernel_launch(void* const* d_in, const int* in_sizes, int n_in,
                              void* d_out, int out_size)
{
    // Identify inputs by element count — robust to d_in ordering.
    int imax = 0, imin = 0;
    for (int i = 1; i < 3 && i < n_in; i++) {
        if (in_sizes[i] > in_sizes[imax]) imax = i;
        if (in_sizes[i] < in_sizes[imin]) imin = i;
    }
    const int imid = 3 - imax - imin;

    const float* features = (const float*)d_in[imax];
    const float* W        = (const float*)d_in[imin];
    const int*   sample   = (const int*)d_in[imid];

    float* out = (float*)d_out;

    const int n_rows = in_sizes[imid] / S_SAMPLES;   // 32768
    const int grid   = n_rows / ROWS;                // 512

    const int smem_bytes = (2 * SA_ELEMS + 2 * SW_ELEMS) * sizeof(__nv_bfloat16);
    // = 104,448 B

    cudaFuncSetAttribute(gcn_agg_kernel,
                         cudaFuncAttributeMaxDynamicSharedMemorySize,
                         smem_bytes);

    gcn_agg_kernel<<<grid, THREADS, smem_bytes>>>(features, sample, W, out);
}

// round 9
// speedup vs baseline: 1.7646x; 1.0457x over previous
#include <cuda_runtime.h>
#include <cuda_bf16.h>
#include <mma.h>
#include <cstdint>

using namespace nvcuda;

// GCNAggregator split:
//   K1: mean[row] = mean_s features[sample[row][s]]      (streaming gather)
//   K2: out[row]  = relu( mean[row] @ W )                (bf16-split WMMA)
// mean is staged in d_out (each block of K2 reads its own rows into smem
// before overwriting them -> no hazard).

#define D_DIM 128
#define S_SAMPLES 25
#define N_NODES 100000

// ---------------- K1: gather + mean ----------------
#define K1_THREADS 256
#define K1_WARPS 8
#define K1_GRID 1024          // 1024*8 warps * 4 rows = 32768 rows

__global__ __launch_bounds__(K1_THREADS)
void gather_mean_kernel(const float* __restrict__ features,
                        const int* __restrict__ sample,
                        float* __restrict__ mean_out)
{
    const int wid  = threadIdx.x >> 5;
    const int lane = threadIdx.x & 31;
    const int k0   = lane * 4;
    const int wglobal = blockIdx.x * K1_WARPS + wid;   // 0..8191

    #pragma unroll
    for (int r = 0; r < 4; r++) {
        const int row = wglobal + r * (K1_GRID * K1_WARPS);
        const int* idxp = sample + (long long)row * S_SAMPLES;

        float4 acc = make_float4(0.f, 0.f, 0.f, 0.f);
        #pragma unroll
        for (int s = 0; s < S_SAMPLES; s++) {
            int node = __ldg(&idxp[s]);                 // uniform broadcast
            node = min(max(node, 0), N_NODES - 1);      // defensive clamp
            const float4 v = *reinterpret_cast<const float4*>(
                &features[(long long)node * D_DIM + k0]);
            acc.x += v.x; acc.y += v.y; acc.z += v.z; acc.w += v.w;
        }
        const float inv = 1.0f / (float)S_SAMPLES;
        acc.x *= inv; acc.y *= inv; acc.z *= inv; acc.w *= inv;
        *reinterpret_cast<float4*>(&mean_out[(long long)row * D_DIM + k0]) = acc;
    }
}

// ---------------- K2: WMMA GEMM + relu ----------------
#define THREADS 256
#define ROWS 64
#define LDS_A 136                    // padded bf16 stride (272 B rows)
#define SA_ELEMS (ROWS * LDS_A)      // 8704
#define SW_ELEMS (D_DIM * LDS_A)     // 17408

__global__ __launch_bounds__(THREADS, 2)
void gemm_relu_kernel(const float* __restrict__ W,
                      float* __restrict__ inout)   // mean in, relu(out) out
{
    extern __shared__ __nv_bfloat16 smem[];
    __nv_bfloat16* sAhi = smem;                         // [64][136]
    __nv_bfloat16* sAlo = sAhi + SA_ELEMS;
    __nv_bfloat16* sWhi = sAlo + SA_ELEMS;              // [128][136]
    __nv_bfloat16* sWlo = sWhi + SW_ELEMS;

    const int tid  = threadIdx.x;
    const int wid  = tid >> 5;
    const int row0 = blockIdx.x * ROWS;

    // ---- Stage W -> bf16 hi/lo (coalesced float4) ----
    #pragma unroll
    for (int i = 0; i < 16; i++) {
        const int idx = tid + i * THREADS;        // 0..4095 float4
        const int k   = idx >> 5;
        const int n0  = (idx & 31) * 4;
        const float4 v = *reinterpret_cast<const float4*>(&W[k * D_DIM + n0]);

        __nv_bfloat16 hx = __float2bfloat16(v.x), hy = __float2bfloat16(v.y);
        __nv_bfloat16 hz = __float2bfloat16(v.z), hw = __float2bfloat16(v.w);
        *reinterpret_cast<__nv_bfloat162*>(&sWhi[k * LDS_A + n0]) =
            __nv_bfloat162(hx, hy);
        *reinterpret_cast<__nv_bfloat162*>(&sWhi[k * LDS_A + n0 + 2]) =
            __nv_bfloat162(hz, hw);
        *reinterpret_cast<__nv_bfloat162*>(&sWlo[k * LDS_A + n0]) =
            __nv_bfloat162(__float2bfloat16(v.x - __bfloat162float(hx)),
                           __float2bfloat16(v.y - __bfloat162float(hy)));
        *reinterpret_cast<__nv_bfloat162*>(&sWlo[k * LDS_A + n0 + 2]) =
            __nv_bfloat162(__float2bfloat16(v.z - __bfloat162float(hz)),
                           __float2bfloat16(v.w - __bfloat162float(hw)));
    }

    // ---- Stage A (means) -> bf16 hi/lo (coalesced float4 from inout) ----
    #pragma unroll
    for (int i = 0; i < 8; i++) {
        const int idx = tid + i * THREADS;        // 0..2047 float4
        const int rr  = idx >> 5;                 // 0..63
        const int k0  = (idx & 31) * 4;
        const float4 v = *reinterpret_cast<const float4*>(
            &inout[(long long)(row0 + rr) * D_DIM + k0]);

        __nv_bfloat16 hx = __float2bfloat16(v.x), hy = __float2bfloat16(v.y);
        __nv_bfloat16 hz = __float2bfloat16(v.z), hw = __float2bfloat16(v.w);
        *reinterpret_cast<__nv_bfloat162*>(&sAhi[rr * LDS_A + k0]) =
            __nv_bfloat162(hx, hy);
        *reinterpret_cast<__nv_bfloat162*>(&sAhi[rr * LDS_A + k0 + 2]) =
            __nv_bfloat162(hz, hw);
        *reinterpret_cast<__nv_bfloat162*>(&sAlo[rr * LDS_A + k0]) =
            __nv_bfloat162(__float2bfloat16(v.x - __bfloat162float(hx)),
                           __float2bfloat16(v.y - __bfloat162float(hy)));
        *reinterpret_cast<__nv_bfloat162*>(&sAlo[rr * LDS_A + k0 + 2]) =
            __nv_bfloat162(__float2bfloat16(v.z - __bfloat162float(hz)),
                           __float2bfloat16(v.w - __bfloat162float(hw)));
    }
    __syncthreads();

    // ---- WMMA GEMM [64,128] x [128,128], 3-term bf16 split ----
    const int wr = (wid >> 2) * 32;   // 0 or 32
    const int wc = (wid & 3) * 32;    // 0,32,64,96

    wmma::fragment<wmma::accumulator, 16, 16, 16, float> acc[2][2];
    #pragma unroll
    for (int i = 0; i < 2; i++)
        #pragma unroll
        for (int j = 0; j < 2; j++)
            wmma::fill_fragment(acc[i][j], 0.0f);

    #pragma unroll
    for (int ks = 0; ks < D_DIM / 16; ks++) {
        wmma::fragment<wmma::matrix_a, 16, 16, 16, __nv_bfloat16,
                       wmma::row_major> aHi[2], aLo[2];
        wmma::fragment<wmma::matrix_b, 16, 16, 16, __nv_bfloat16,
                       wmma::row_major> bHi[2], bLo[2];

        #pragma unroll
        for (int i = 0; i < 2; i++) {
            const __nv_bfloat16* pa = &sAhi[(wr + i * 16) * LDS_A + ks * 16];
            wmma::load_matrix_sync(aHi[i], pa, LDS_A);
            wmma::load_matrix_sync(aLo[i], pa + SA_ELEMS, LDS_A);   // sAlo
        }
        #pragma unroll
        for (int j = 0; j < 2; j++) {
            const __nv_bfloat16* pb = &sWhi[(ks * 16) * LDS_A + wc + j * 16];
            wmma::load_matrix_sync(bHi[j], pb, LDS_A);
            wmma::load_matrix_sync(bLo[j], pb + SW_ELEMS, LDS_A);   // sWlo
        }

        #pragma unroll
        for (int i = 0; i < 2; i++)
            #pragma unroll
            for (int j = 0; j < 2; j++) {
                wmma::mma_sync(acc[i][j], aHi[i], bHi[j], acc[i][j]);
                wmma::mma_sync(acc[i][j], aHi[i], bLo[j], acc[i][j]);
                wmma::mma_sync(acc[i][j], aLo[i], bHi[j], acc[i][j]);
            }
    }

    // ---- Epilogue: relu + store (overwrites this block's own rows) ----
    #pragma unroll
    for (int i = 0; i < 2; i++)
        #pragma unroll
        for (int j = 0; j < 2; j++) {
            #pragma unroll
            for (int t = 0; t < acc[i][j].num_elements; t++)
                acc[i][j].x[t] = fmaxf(acc[i][j].x[t], 0.0f);
            wmma::store_matrix_sync(
                &inout[(long long)(row0 + wr + i * 16) * D_DIM + wc + j * 16],
                acc[i][j], D_DIM, wmma::mem_row_major);
        }
}

extern "C" void kernel_launch(void* const* d_in, const int* in_sizes, int n_in,
                              void* d_out, int out_size)
{
    // Identify inputs by element count — robust to d_in ordering.
    int imax = 0, imin = 0;
    for (int i = 1; i < 3 && i < n_in; i++) {
        if (in_sizes[i] > in_sizes[imax]) imax = i;
        if (in_sizes[i] < in_sizes[imin]) imin = i;
    }
    const int imid = 3 - imax - imin;

    const float* features = (const float*)d_in[imax];
    const float* W        = (const float*)d_in[imin];
    const int*   sample   = (const int*)d_in[imid];

    float* out = (float*)d_out;

    const int n_rows = in_sizes[imid] / S_SAMPLES;   // 32768
    const int grid2  = n_rows / ROWS;                // 512

    const int smem_bytes = (2 * SA_ELEMS + 2 * SW_ELEMS) * sizeof(__nv_bfloat16);

    cudaFuncSetAttribute(gemm_relu_kernel,
                         cudaFuncAttributeMaxDynamicSharedMemorySize,
                         smem_bytes);

    gather_mean_kernel<<<K1_GRID, K1_THREADS>>>(features, sample, out);
    gemm_relu_kernel<<<grid2, THREADS, smem_bytes>>>(W, out);
}